// round 8
// baseline (speedup 1.0000x reference)
#include <cuda_runtime.h>

// S4D diagonal SSM: out[h,l] = 2*Re( sum_n cmod[h,n] * z[h,n]^l ),  z = exp(w*dt)
// Factor l = 64k + j (k in [0,32), j in [0,64)):
//   out[h,64k+j] = sum_n ( Bre[n,k]*Are[n,j] - Bim[n,k]*Aim[n,j] )
// Packing: A[n][j]=(ar,ai) float2, B[k][n]=(br,-bi) float2.
// fma.rn.f32x2 acc += B ⊗ A accumulates {Σ br*ar, Σ -bi*ai}; out = lo+hi.
// R8: 32 thr/block, 8k x 8j tile per thread -> LDS/FFMA2 = 0.125, the balanced
//     point where smem-crossbar time equals fma-pipe time (14.2K cyc each).

#define HDIM 1024
#define NDIM 64
#define LLEN 2048

#define AST 66                       // A row stride in float2 (64 + 2 pad; 528 B)
#define BST 66                       // B row stride in float2 (528 B)
#define A_FLOATS (64*AST*2)          // 8448 floats (33792 B)
#define B_FLOATS (32*BST*2)          // 4224 floats (16896 B)
#define SMEM_FLOATS (A_FLOATS + B_FLOATS)   // 12672 floats = 50688 B

struct c2 { float re, im; };
__device__ __forceinline__ c2 cmul(c2 a, c2 b) {
    return { fmaf(a.re, b.re, -a.im*b.im), fmaf(a.re, b.im, a.im*b.re) };
}

__device__ __forceinline__ void fma2(unsigned long long& d,
                                     unsigned long long a,
                                     unsigned long long b) {
    asm("fma.rn.f32x2 %0, %1, %2, %0;" : "+l"(d) : "l"(a), "l"(b));
}

union U2 { unsigned long long u; float2 f; };

__global__ __launch_bounds__(32) void ssk_diag_kernel(
    const float* __restrict__ log_dt,
    const float* __restrict__ log_w_real,
    const float* __restrict__ w_imag,
    const float* __restrict__ C_re,
    const float* __restrict__ C_im,
    float* __restrict__ out)
{
    extern __shared__ float sm[];
    float2* sA = reinterpret_cast<float2*>(sm);              // [64 n][AST]
    float2* sB = reinterpret_cast<float2*>(sm + A_FLOATS);   // [32 k][BST]

    const int h   = blockIdx.x;
    const int tid = threadIdx.x;

    // ------------- Phase 1: tables. 32 threads, 2 n per thread ---------------------
    #pragma unroll
    for (int nn = 0; nn < 2; nn++) {
        const int n = tid + 32*nn;

        const float dtv = expf(log_dt[h]);
        const float wre = -expf(log_w_real[h*NDIM + n]);
        const float wim = w_imag[h*NDIM + n];
        const float are = wre * dtv;
        const float aim = wim * dtv;

        const float er = expf(are);
        float s, c; sincosf(aim, &s, &c);
        const c2 z = { er*c, er*s };

        // cmod = 2 * C * (z - 1) / w  (fold output factor 2)
        const float nre = z.re - 1.0f, nim = z.im;
        const float inv = 1.0f / (wre*wre + wim*wim);
        const float tre = (nre*wre + nim*wim) * inv;
        const float tim = (nim*wre - nre*wim) * inv;
        const float cr = C_re[h*NDIM + n], ci = C_im[h*NDIM + n];
        const c2 cm = { 2.0f*(cr*tre - ci*tim), 2.0f*(cr*tim + ci*tre) };

        // power ladder by squaring
        const c2 z2    = cmul(z,    z);
        const c2 z4    = cmul(z2,   z2);
        const c2 z8    = cmul(z4,   z4);
        const c2 z16   = cmul(z8,   z8);
        const c2 z32   = cmul(z16,  z16);
        const c2 z64   = cmul(z32,  z32);
        const c2 z128  = cmul(z64,  z64);
        const c2 z256  = cmul(z128, z128);
        const c2 z512  = cmul(z256, z256);
        const c2 z1024 = cmul(z512, z512);

        // A[n][j]: two independent 32-long chains (ILP)
        c2 a0 = {1.0f, 0.0f};
        c2 a1 = z32;
        #pragma unroll
        for (int jj = 0; jj < 32; jj++) {
            sA[n*AST + jj]      = make_float2(a0.re, a0.im);
            sA[n*AST + 32 + jj] = make_float2(a1.re, a1.im);
            a0 = cmul(a0, z);
            a1 = cmul(a1, z);
        }

        // B[k][n]: two independent 16-long chains
        c2 b0 = cm;
        c2 b1 = cmul(cm, z1024);
        #pragma unroll
        for (int kk = 0; kk < 16; kk++) {
            sB[kk*BST + n]        = make_float2(b0.re, -b0.im);
            sB[(16 + kk)*BST + n] = make_float2(b1.re, -b1.im);
            b0 = cmul(b0, z64);
            b1 = cmul(b1, z64);
        }
    }
    __syncthreads();

    // ------------- Phase 2: contraction. tid = jp*4 + kq ---------------------------
    // Thread tile: k = kq + 4*kk (kk 0..7), j = 8*jp + jj (jj 0..7). 64 outputs.
    const int jp = tid >> 2;    // 0..7
    const int kq = tid & 3;     // 0..3

    const char* pA = reinterpret_cast<const char*>(sA) + (size_t)jp * 64;
    const char* pB = reinterpret_cast<const char*>(sB) + (size_t)kq * (BST*8);

    unsigned long long acc[8][8];   // [kk][jj] -> 128 regs
    #pragma unroll
    for (int i = 0; i < 8; i++)
        #pragma unroll
        for (int jj = 0; jj < 8; jj++) acc[i][jj] = 0ull;

    #define LDA(off) (*reinterpret_cast<const ulonglong2*>(pA + (off)))
    #define LDB(off) (*reinterpret_cast<const ulonglong2*>(pB + (off)))

    #pragma unroll 8
    for (int n2 = 0; n2 < 32; n2++) {
        const int na = 2*n2, nb = 2*n2 + 1;
        // A: 4 LDS.128 per n cover 8 j's
        const ulonglong2 aa0 = LDA((size_t)na*AST*8);
        const ulonglong2 aa1 = LDA((size_t)na*AST*8 + 16);
        const ulonglong2 aa2 = LDA((size_t)na*AST*8 + 32);
        const ulonglong2 aa3 = LDA((size_t)na*AST*8 + 48);
        const ulonglong2 ab0 = LDA((size_t)nb*AST*8);
        const ulonglong2 ab1 = LDA((size_t)nb*AST*8 + 16);
        const ulonglong2 ab2 = LDA((size_t)nb*AST*8 + 32);
        const ulonglong2 ab3 = LDA((size_t)nb*AST*8 + 48);
        // B: rows k = kq + 4*kk; each 16B covers (na, nb)
        ulonglong2 b[8];
        #pragma unroll
        for (int kk = 0; kk < 8; kk++)
            b[kk] = LDB((size_t)kk*(4*BST*8) + (size_t)na*8);

        #pragma unroll
        for (int kk = 0; kk < 8; kk++) {
            fma2(acc[kk][0], b[kk].x, aa0.x);
            fma2(acc[kk][1], b[kk].x, aa0.y);
            fma2(acc[kk][2], b[kk].x, aa1.x);
            fma2(acc[kk][3], b[kk].x, aa1.y);
            fma2(acc[kk][4], b[kk].x, aa2.x);
            fma2(acc[kk][5], b[kk].x, aa2.y);
            fma2(acc[kk][6], b[kk].x, aa3.x);
            fma2(acc[kk][7], b[kk].x, aa3.y);
            fma2(acc[kk][0], b[kk].y, ab0.x);
            fma2(acc[kk][1], b[kk].y, ab0.y);
            fma2(acc[kk][2], b[kk].y, ab1.x);
            fma2(acc[kk][3], b[kk].y, ab1.y);
            fma2(acc[kk][4], b[kk].y, ab2.x);
            fma2(acc[kk][5], b[kk].y, ab2.y);
            fma2(acc[kk][6], b[kk].y, ab3.x);
            fma2(acc[kk][7], b[kk].y, ab3.y);
        }
    }
    #undef LDA
    #undef LDB

    // Reduce packed halves; store: l = 64*(kq+4*kk) + 8*jp + jj  (2x float4 per kk)
    float* po = out + h*LLEN + kq*64 + jp*8;
    #pragma unroll
    for (int kk = 0; kk < 8; kk++) {
        float4 v0, v1;
        { U2 u; u.u = acc[kk][0]; v0.x = u.f.x + u.f.y; }
        { U2 u; u.u = acc[kk][1]; v0.y = u.f.x + u.f.y; }
        { U2 u; u.u = acc[kk][2]; v0.z = u.f.x + u.f.y; }
        { U2 u; u.u = acc[kk][3]; v0.w = u.f.x + u.f.y; }
        { U2 u; u.u = acc[kk][4]; v1.x = u.f.x + u.f.y; }
        { U2 u; u.u = acc[kk][5]; v1.y = u.f.x + u.f.y; }
        { U2 u; u.u = acc[kk][6]; v1.z = u.f.x + u.f.y; }
        { U2 u; u.u = acc[kk][7]; v1.w = u.f.x + u.f.y; }
        *reinterpret_cast<float4*>(po + kk*256)     = v0;
        *reinterpret_cast<float4*>(po + kk*256 + 4) = v1;
    }
}

extern "C" void kernel_launch(void* const* d_in, const int* in_sizes, int n_in,
                              void* d_out, int out_size)
{
    const float* log_dt     = (const float*)d_in[0];
    const float* log_w_real = (const float*)d_in[1];
    const float* w_imag     = (const float*)d_in[2];
    const float* C_re       = (const float*)d_in[3];
    const float* C_im       = (const float*)d_in[4];
    float* out = (float*)d_out;

    const int smem_bytes = SMEM_FLOATS * (int)sizeof(float);   // 50688 B
    cudaFuncSetAttribute(ssk_diag_kernel,
                         cudaFuncAttributeMaxDynamicSharedMemorySize, smem_bytes);

    ssk_diag_kernel<<<HDIM, 32, smem_bytes>>>(log_dt, log_w_real, w_imag,
                                              C_re, C_im, out);
}

// round 9
// speedup vs baseline: 1.0631x; 1.0631x over previous
#include <cuda_runtime.h>

// S4D diagonal SSM: out[h,l] = 2*Re( sum_n cmod[h,n] * z[h,n]^l ),  z = exp(w*dt)
// Factor l = 64k + j (k in [0,32), j in [0,64)):
//   out[h,64k+j] = sum_n ( Bre[n,k]*Are[n,j] - Bim[n,k]*Aim[n,j] )
// Packing: A=(ar,ai) float2, B=(br,-bi) float2; fma.rn.f32x2 acc += B ⊗ A
// accumulates {Σ br*ar, Σ -bi*ai}; out = lo+hi.
// R9: FRAGMENT-BLOCKED smem layout. Tables stored in load-instruction order:
//   A2[n][c][jp] : chunk(16B) = (A[n][8jp+2c], A[n][8jp+2c+1])
//   B2[n2][kk][kq]: chunk(16B) = (B[kq+8kk][2*n2], B[kq+8kk][2*n2+1])
// -> every phase-2 LDS.128 is one contiguous 128B warp read: 1 wavefront,
//    zero bank conflicts (vs 4-way conflicts in R5-R8 layouts).

#define HDIM 1024
#define NDIM 64
#define LLEN 2048

#define AROW 528                     // bytes per A2 n-row (512 + 16 pad: de-conflicts STS)
#define BROW 528                     // bytes per B2 n2-row
#define A_BYTES (64*AROW)            // 33792
#define B_BYTES (32*BROW)            // 16896
#define SMEM_BYTES (A_BYTES + B_BYTES)   // 50688

struct c2 { float re, im; };
__device__ __forceinline__ c2 cmul(c2 a, c2 b) {
    return { fmaf(a.re, b.re, -a.im*b.im), fmaf(a.re, b.im, a.im*b.re) };
}

__device__ __forceinline__ void fma2(unsigned long long& d,
                                     unsigned long long a,
                                     unsigned long long b) {
    asm("fma.rn.f32x2 %0, %1, %2, %0;" : "+l"(d) : "l"(a), "l"(b));
}

union U2 { unsigned long long u; float2 f; };

__global__ __launch_bounds__(64, 4) void ssk_diag_kernel(
    const float* __restrict__ log_dt,
    const float* __restrict__ log_w_real,
    const float* __restrict__ w_imag,
    const float* __restrict__ C_re,
    const float* __restrict__ C_im,
    float* __restrict__ out)
{
    extern __shared__ char smem[];
    char* A2 = smem;             // [64 n][4 c][8 jp] 16B chunks, row stride AROW
    char* B2 = smem + A_BYTES;   // [32 n2][4 kk][8 kq] 16B chunks, row stride BROW

    const int h   = blockIdx.x;
    const int tid = threadIdx.x;

    // ------------- Phase 1: tables. One n per thread --------------------------------
    {
        const int n = tid;   // 0..63

        const float dtv = expf(log_dt[h]);
        const float wre = -expf(log_w_real[h*NDIM + n]);
        const float wim = w_imag[h*NDIM + n];
        const float are = wre * dtv;
        const float aim = wim * dtv;

        const float er = expf(are);
        float s, c; sincosf(aim, &s, &c);
        const c2 z = { er*c, er*s };

        // cmod = 2 * C * (z - 1) / w  (fold output factor 2)
        const float nre = z.re - 1.0f, nim = z.im;
        const float inv = 1.0f / (wre*wre + wim*wim);
        const float tre = (nre*wre + nim*wim) * inv;
        const float tim = (nim*wre - nre*wim) * inv;
        const float cr = C_re[h*NDIM + n], ci = C_im[h*NDIM + n];
        const c2 cm = { 2.0f*(cr*tre - ci*tim), 2.0f*(cr*tim + ci*tre) };

        // power ladder by squaring
        const c2 z2    = cmul(z,    z);
        const c2 z4    = cmul(z2,   z2);
        const c2 z8    = cmul(z4,   z4);
        const c2 z16   = cmul(z8,   z8);
        const c2 z32   = cmul(z16,  z16);
        const c2 z64   = cmul(z32,  z32);
        const c2 z128  = cmul(z64,  z64);
        const c2 z256  = cmul(z128, z128);
        const c2 z512  = cmul(z256, z256);
        const c2 z1024 = cmul(z512, z512);

        // A chunks: j -> (c = (j&7)>>1, jp = j>>3, parity = j&1)
        // Two independent chains: j from 0, and j+32 (same c/parity, jp+4 = +64B)
        c2 a0 = {1.0f, 0.0f};
        c2 a1 = z32;
        char* arow = A2 + n*AROW;
        #pragma unroll
        for (int jj = 0; jj < 32; jj++) {
            const int off = ((jj & 7) >> 1)*128 + (jj >> 3)*16 + (jj & 1)*8;
            *reinterpret_cast<float2*>(arow + off)      = make_float2(a0.re, a0.im);
            *reinterpret_cast<float2*>(arow + off + 64) = make_float2(a1.re, a1.im);
            a0 = cmul(a0, z);
            a1 = cmul(a1, z);
        }

        // B chunks: k -> (kk = k>>3, kq = k&7), n -> (row n>>1, parity n&1)
        // Two independent chains: k from 0, and k+16 (kk+2 = +256B)
        c2 b0 = cm;
        c2 b1 = cmul(cm, z1024);
        char* brow = B2 + (n >> 1)*BROW + (n & 1)*8;
        #pragma unroll
        for (int k = 0; k < 16; k++) {
            const int off = (k >> 3)*128 + (k & 7)*16;
            *reinterpret_cast<float2*>(brow + off)       = make_float2(b0.re, -b0.im);
            *reinterpret_cast<float2*>(brow + off + 256) = make_float2(b1.re, -b1.im);
            b0 = cmul(b0, z64);
            b1 = cmul(b1, z64);
        }
    }
    __syncthreads();

    // ------------- Phase 2: contraction. tid = jp*8 + kq ---------------------------
    // Thread tile: k = kq + 8*kk (kk 0..3), j = 8*jp + jj (jj 0..7). 32 outputs.
    const int jp = tid >> 3;    // 0..7
    const int kq = tid & 7;     // 0..7

    const char* pA = A2 + jp*16;   // + n*AROW + c*128 : contiguous 128B across warp
    const char* pB = B2 + kq*16;   // + n2*BROW + kk*128: contiguous 128B across warp

    unsigned long long acc[4][8];   // [kk][jj] -> 64 regs
    #pragma unroll
    for (int i = 0; i < 4; i++)
        #pragma unroll
        for (int jj = 0; jj < 8; jj++) acc[i][jj] = 0ull;

    #define LDA(off) (*reinterpret_cast<const ulonglong2*>(pA + (off)))
    #define LDB(off) (*reinterpret_cast<const ulonglong2*>(pB + (off)))

    #pragma unroll 8
    for (int n2 = 0; n2 < 32; n2++) {
        const int na = 2*n2, nb = 2*n2 + 1;
        // A: 4 chunks per n (c=0..3), 1 wavefront each
        ulonglong2 aa[4], ab[4], b[4];
        #pragma unroll
        for (int c = 0; c < 4; c++) {
            aa[c] = LDA(na*AROW + c*128);
            ab[c] = LDA(nb*AROW + c*128);
            b[c]  = LDB(n2*BROW + c*128);   // b[kk]: .x = B[k][na], .y = B[k][nb]
        }

        #pragma unroll
        for (int kk = 0; kk < 4; kk++) {
            #pragma unroll
            for (int c = 0; c < 4; c++) {
                fma2(acc[kk][2*c],     b[kk].x, aa[c].x);
                fma2(acc[kk][2*c + 1], b[kk].x, aa[c].y);
                fma2(acc[kk][2*c],     b[kk].y, ab[c].x);
                fma2(acc[kk][2*c + 1], b[kk].y, ab[c].y);
            }
        }
    }
    #undef LDA
    #undef LDB

    // Reduce packed halves; store: l = 64*(kq+8*kk) + 8*jp + jj  (2x float4 per kk)
    float* po = out + h*LLEN + kq*64 + jp*8;
    #pragma unroll
    for (int kk = 0; kk < 4; kk++) {
        float4 v0, v1;
        { U2 u; u.u = acc[kk][0]; v0.x = u.f.x + u.f.y; }
        { U2 u; u.u = acc[kk][1]; v0.y = u.f.x + u.f.y; }
        { U2 u; u.u = acc[kk][2]; v0.z = u.f.x + u.f.y; }
        { U2 u; u.u = acc[kk][3]; v0.w = u.f.x + u.f.y; }
        { U2 u; u.u = acc[kk][4]; v1.x = u.f.x + u.f.y; }
        { U2 u; u.u = acc[kk][5]; v1.y = u.f.x + u.f.y; }
        { U2 u; u.u = acc[kk][6]; v1.z = u.f.x + u.f.y; }
        { U2 u; u.u = acc[kk][7]; v1.w = u.f.x + u.f.y; }
        *reinterpret_cast<float4*>(po + kk*512)     = v0;
        *reinterpret_cast<float4*>(po + kk*512 + 4) = v1;
    }
}

extern "C" void kernel_launch(void* const* d_in, const int* in_sizes, int n_in,
                              void* d_out, int out_size)
{
    const float* log_dt     = (const float*)d_in[0];
    const float* log_w_real = (const float*)d_in[1];
    const float* w_imag     = (const float*)d_in[2];
    const float* C_re       = (const float*)d_in[3];
    const float* C_im       = (const float*)d_in[4];
    float* out = (float*)d_out;

    cudaFuncSetAttribute(ssk_diag_kernel,
                         cudaFuncAttributeMaxDynamicSharedMemorySize, SMEM_BYTES);

    ssk_diag_kernel<<<HDIM, 64, SMEM_BYTES>>>(log_dt, log_w_real, w_imag,
                                              C_re, C_im, out);
}

// round 11
// speedup vs baseline: 1.2292x; 1.1563x over previous
#include <cuda_runtime.h>
#include <cuda_bf16.h>
#include <cstdint>

// S4D diagonal SSM via split-precision bf16 mma.sync (HMMA, sm_80+ -> legal on sm_100).
// Factor l = 64k + j (k in [0,32), j in [0,64)):
//   out[h,64k+j] = sum_n ( Bre[k,n]*Are[n,j] - Bim[k,n]*Aim[n,j] ) = D[j][k]
//   D[128][32] = Aop[128x128] . Bop[32x128]^T,  reduction dim = 2n interleaved (re,im)
// Aop rows 0-63 = bf16_hi(Are,Aim), rows 64-127 = bf16_lo residual.
// Bop hi/lo tiles rows k: (Bre, -Bim). Two accumulating passes => D=(Ah+Al)(Bh+Bl)
// split across row halves; epilogue out[j][k] = D[j][k] + D[j+64][k]. Err ~2^-18.

#define HDIM 1024
#define NDIM 64
#define LLEN 2048

#define AROWB 272      // A row stride bytes (128 bf16 cols + 8 pad) ; 68 words = 4 mod 32
#define BROWB 272      // B row stride bytes
#define SM_A   0                        // 128 x AROWB = 34816 B (reused as fp32 stage)
#define SM_BH  (128*AROWB)              // 32 x BROWB = 8704 B
#define SM_BL  (SM_BH + 32*BROWB)
#define SM_TOTAL (SM_BL + 32*BROWB)     // 52224 B

struct c2 { float re, im; };
__device__ __forceinline__ c2 cmul(c2 a, c2 b) {
    return { fmaf(a.re, b.re, -a.im*b.im), fmaf(a.re, b.im, a.im*b.re) };
}

__device__ __forceinline__ void mma16816(float* c, const uint32_t* a, const uint32_t* b) {
    asm volatile(
        "mma.sync.aligned.m16n8k16.row.col.f32.bf16.bf16.f32 "
        "{%0,%1,%2,%3}, {%4,%5,%6,%7}, {%8,%9}, {%0,%1,%2,%3};"
        : "+f"(c[0]), "+f"(c[1]), "+f"(c[2]), "+f"(c[3])
        : "r"(a[0]), "r"(a[1]), "r"(a[2]), "r"(a[3]), "r"(b[0]), "r"(b[1]));
}

__global__ __launch_bounds__(128) void ssk_diag_kernel(
    const float* __restrict__ log_dt,
    const float* __restrict__ log_w_real,
    const float* __restrict__ w_imag,
    const float* __restrict__ C_re,
    const float* __restrict__ C_im,
    float* __restrict__ out)
{
    extern __shared__ char smem[];
    const int h   = blockIdx.x;
    const int tid = threadIdx.x;
    const int wid = tid >> 5;
    const int lid = tid & 31;

    // ------------- Phase 1: build bf16 hi/lo operand tiles --------------------------
    {
        const int n    = tid & 63;
        const int half = tid >> 6;

        const float dtv = expf(log_dt[h]);
        const float wre = -expf(log_w_real[h*NDIM + n]);
        const float wim = w_imag[h*NDIM + n];
        const float er  = expf(wre * dtv);
        float s, c; sincosf(wim * dtv, &s, &c);
        const c2 z = { er*c, er*s };

        // cmod = 2 * C * (z - 1) / w  (fold the output factor of 2)
        const float nre = z.re - 1.0f, nim = z.im;
        const float inv = 1.0f / (wre*wre + wim*wim);
        const float tre = (nre*wre + nim*wim) * inv;
        const float tim = (nim*wre - nre*wim) * inv;
        const float cr = C_re[h*NDIM + n], ci = C_im[h*NDIM + n];
        const c2 cm = { 2.0f*(cr*tre - ci*tim), 2.0f*(cr*tim + ci*tre) };

        // power ladder by squaring
        const c2 z2    = cmul(z,    z);
        const c2 z4    = cmul(z2,   z2);
        const c2 z8    = cmul(z4,   z4);
        const c2 z16   = cmul(z8,   z8);
        const c2 z32   = cmul(z16,  z16);
        const c2 z64   = cmul(z32,  z32);
        const c2 z128  = cmul(z64,  z64);
        const c2 z256  = cmul(z128, z128);
        const c2 z512  = cmul(z256, z256);
        const c2 z1024 = cmul(z512, z512);

        // A operand: row j (hi) / j+64 (lo), cols (2n, 2n+1) = (Are, Aim)
        c2 a = half ? z32 : c2{1.0f, 0.0f};
        #pragma unroll
        for (int jj = 0; jj < 32; jj++) {
            const int j = 32*half + jj;
            const __nv_bfloat16 hr = __float2bfloat16_rn(a.re);
            const __nv_bfloat16 hi = __float2bfloat16_rn(a.im);
            const float lr = a.re - __bfloat162float(hr);
            const float li = a.im - __bfloat162float(hi);
            *reinterpret_cast<__nv_bfloat162*>(smem + SM_A + j*AROWB + 4*n) =
                __nv_bfloat162(hr, hi);
            *reinterpret_cast<__nv_bfloat162*>(smem + SM_A + (j+64)*AROWB + 4*n) =
                __floats2bfloat162_rn(lr, li);
            a = cmul(a, z);
        }

        // B operand: row k, cols (2n, 2n+1) = (Bre, -Bim); hi and lo tiles
        c2 b = half ? cmul(cm, z1024) : cm;
        #pragma unroll
        for (int kk = 0; kk < 16; kk++) {
            const int k = 16*half + kk;
            const float bre = b.re, bim = -b.im;
            const __nv_bfloat16 hr = __float2bfloat16_rn(bre);
            const __nv_bfloat16 hi = __float2bfloat16_rn(bim);
            *reinterpret_cast<__nv_bfloat162*>(smem + SM_BH + k*BROWB + 4*n) =
                __nv_bfloat162(hr, hi);
            *reinterpret_cast<__nv_bfloat162*>(smem + SM_BL + k*BROWB + 4*n) =
                __floats2bfloat162_rn(bre - __bfloat162float(hr),
                                      bim - __bfloat162float(hi));
            b = cmul(b, z64);
        }
    }
    __syncthreads();

    // ------------- Phase 2: mma.sync contraction ------------------------------------
    // Warp w: M rows [32w, 32w+32). 2 m16 tiles x 4 n8 tiles x 8 k16 steps x 2 passes.
    const int g = lid >> 2;     // 0..7  (group / row-in-tile)
    const int t = lid & 3;      // 0..3  (thread-in-group / col pair)
    const int mbase = wid * 32;

    float acc[2][4][4];
    #pragma unroll
    for (int mt = 0; mt < 2; mt++)
        #pragma unroll
        for (int nt = 0; nt < 4; nt++)
            #pragma unroll
            for (int i = 0; i < 4; i++) acc[mt][nt][i] = 0.0f;

    #pragma unroll
    for (int s = 0; s < 8; s++) {
        const int k0 = 16*s;

        uint32_t af[2][4];
        #pragma unroll
        for (int mt = 0; mt < 2; mt++) {
            const int r = mbase + mt*16 + g;
            af[mt][0] = *reinterpret_cast<const uint32_t*>(smem + SM_A + r*AROWB     + (k0 + 2*t)*2);
            af[mt][1] = *reinterpret_cast<const uint32_t*>(smem + SM_A + (r+8)*AROWB + (k0 + 2*t)*2);
            af[mt][2] = *reinterpret_cast<const uint32_t*>(smem + SM_A + r*AROWB     + (k0 + 2*t + 8)*2);
            af[mt][3] = *reinterpret_cast<const uint32_t*>(smem + SM_A + (r+8)*AROWB + (k0 + 2*t + 8)*2);
        }
        uint32_t bh[4][2], bl[4][2];
        #pragma unroll
        for (int nt = 0; nt < 4; nt++) {
            const int n = nt*8 + g;
            bh[nt][0] = *reinterpret_cast<const uint32_t*>(smem + SM_BH + n*BROWB + (k0 + 2*t)*2);
            bh[nt][1] = *reinterpret_cast<const uint32_t*>(smem + SM_BH + n*BROWB + (k0 + 2*t + 8)*2);
            bl[nt][0] = *reinterpret_cast<const uint32_t*>(smem + SM_BL + n*BROWB + (k0 + 2*t)*2);
            bl[nt][1] = *reinterpret_cast<const uint32_t*>(smem + SM_BL + n*BROWB + (k0 + 2*t + 8)*2);
        }

        #pragma unroll
        for (int mt = 0; mt < 2; mt++)
            #pragma unroll
            for (int nt = 0; nt < 4; nt++) {
                mma16816(acc[mt][nt], af[mt], bh[nt]);
                mma16816(acc[mt][nt], af[mt], bl[nt]);
            }
    }

    // ------------- Epilogue: stage D (fp32) in retired A region, add halves --------
    __syncthreads();   // all A/B reads complete before overwriting A region
    float* stage = reinterpret_cast<float*>(smem + SM_A);   // [128][33]
    #pragma unroll
    for (int mt = 0; mt < 2; mt++) {
        const int r = mbase + mt*16 + g;
        #pragma unroll
        for (int nt = 0; nt < 4; nt++) {
            const int cb = nt*8 + 2*t;
            stage[r*33 + cb]       = acc[mt][nt][0];
            stage[r*33 + cb + 1]   = acc[mt][nt][1];
            stage[(r+8)*33 + cb]     = acc[mt][nt][2];
            stage[(r+8)*33 + cb + 1] = acc[mt][nt][3];
        }
    }
    __syncthreads();

    // out[h, 64k + j] = stage[j][k] + stage[j+64][k]
    {
        const int k  = tid >> 2;       // 0..31
        const int jg = tid & 3;        // 0..3 -> j base = 16*jg
        float* po = out + (size_t)h*LLEN + k*64 + jg*16;
        #pragma unroll
        for (int q = 0; q < 4; q++) {
            const int j = jg*16 + q*4;
            float4 v;
            v.x = stage[(j+0)*33 + k] + stage[(j+64)*33 + k];
            v.y = stage[(j+1)*33 + k] + stage[(j+65)*33 + k];
            v.z = stage[(j+2)*33 + k] + stage[(j+66)*33 + k];
            v.w = stage[(j+3)*33 + k] + stage[(j+67)*33 + k];
            *reinterpret_cast<float4*>(po + q*4) = v;
        }
    }
}

extern "C" void kernel_launch(void* const* d_in, const int* in_sizes, int n_in,
                              void* d_out, int out_size)
{
    const float* log_dt     = (const float*)d_in[0];
    const float* log_w_real = (const float*)d_in[1];
    const float* w_imag     = (const float*)d_in[2];
    const float* C_re       = (const float*)d_in[3];
    const float* C_im       = (const float*)d_in[4];
    float* out = (float*)d_out;

    cudaFuncSetAttribute(ssk_diag_kernel,
                         cudaFuncAttributeMaxDynamicSharedMemorySize, SM_TOTAL);

    ssk_diag_kernel<<<HDIM, 128, SM_TOTAL>>>(log_dt, log_w_real, w_imag,
                                             C_re, C_im, out);
}